// round 4
// baseline (speedup 1.0000x reference)
#include <cuda_runtime.h>

// ---------------- problem constants ----------------
#define DT_F 0.01f
constexpr int N    = 64;     // state dim
constexpr int RNK  = 4;      // low rank
constexpr int DIN  = 128;
constexpr int DOUT = 128;
constexpr int BATCH = 32;
constexpr int T    = 8192;
constexpr int L    = 128;            // chunk length
constexpr int G    = T / L;          // 64 chunks
constexpr int BT   = BATCH * T;      // 262144
constexpr int PF   = 8;              // scan prefetch depth

// ---------------- device scratch (static, no allocs) ----------------
__device__ float2 g_bu[(size_t)BT * N];      // 128 MB : B_d @ u  (complex)
__device__ float  g_xr[(size_t)BT * N];      // 64 MB  : Re(x_t)
__device__ float2 g_Bd[DIN * N];             // B_d transposed: [i][n]
__device__ float2 g_Da[N];
__device__ float2 g_U[N * RNK];
__device__ float2 g_V[RNK * N];
__device__ float2 g_Ad[N * N];
__device__ float2 g_Atmp[N * N];
__device__ float2 g_csum[BATCH * G * N];
__device__ float2 g_xin[BATCH * G * N];
__device__ float  g_CT[N * DOUT];            // C transposed: [k][o]
__device__ float  g_DT[DIN * DOUT];          // D transposed: [k][o]
__device__ int    g_dflag;

// ---------------- helpers ----------------
__device__ __forceinline__ float2 cfma(float2 a, float2 b, float2 c) { // c + a*b
    float2 r;
    r.x = fmaf(a.x, b.x, fmaf(-a.y, b.y, c.x));
    r.y = fmaf(a.x, b.y, fmaf( a.y, b.x, c.y));
    return r;
}
__device__ __forceinline__ float2 cmulf(float2 a, float2 b) {
    return cfma(a, b, make_float2(0.f, 0.f));
}
__device__ __forceinline__ unsigned long long ffma2(unsigned long long a,
                                                    unsigned long long b,
                                                    unsigned long long c) {
    unsigned long long d;
    asm("fma.rn.f32x2 %0, %1, %2, %3;" : "=l"(d) : "l"(a), "l"(b), "l"(c));
    return d;
}
__device__ __forceinline__ unsigned long long pack2(float x, float y) {
    unsigned long long r;
    asm("mov.b64 %0, {%1, %2};" : "=l"(r) : "f"(x), "f"(y));
    return r;
}
__device__ __forceinline__ float2 unpack2(unsigned long long v) {
    float x, y;
    asm("mov.b64 {%0, %1}, %2;" : "=f"(x), "=f"(y) : "l"(v));
    return make_float2(x, y);
}

// ---------------- setup: Woodbury factors, B_d, dense A_d, transposes, dflag ----------------
__global__ void setup_kernel(const float* __restrict__ lw, const float* __restrict__ zl,
                             const float* __restrict__ P,  const float* __restrict__ Q,
                             const float* __restrict__ Bm, const float* __restrict__ C,
                             const float* __restrict__ D) {
    __shared__ float2 sminv[N];
    __shared__ float2 sS[16];
    __shared__ float2 sK[16];
    __shared__ float2 sW[RNK * DIN];
    __shared__ float  sred[128];
    const float c = 0.5f * DT_F;
    const int t = threadIdx.x;   // 128 threads

    if (t < N) {
        float om = expf(lw[t]);
        float ze = 1.f / (1.f + expf(-zl[t]));
        float lr = -ze * om;
        float li = om * sqrtf(fmaxf(1.f - ze * ze, 1e-8f));
        float mr = 1.f - c * lr;
        float mi = -c * li;
        float inv = 1.f / (mr * mr + mi * mi);
        sminv[t] = make_float2(mr * inv, -mi * inv);
    }
    __syncthreads();

    // S = c * Q^T Minv P  (4x4 complex)
    if (t < 16) {
        int r = t >> 2, s2 = t & 3;
        float2 acc = make_float2(0.f, 0.f);
        for (int k = 0; k < N; k++) {
            float coef = Q[k * RNK + r] * P[k * RNK + s2];
            acc.x += coef * sminv[k].x;
            acc.y += coef * sminv[k].y;
        }
        sS[t] = make_float2(c * acc.x, c * acc.y);
    }
    __syncthreads();

    // K = inv(I4 - S), Gauss-Jordan
    if (t == 0) {
        float2 M_[4][8];
        for (int i = 0; i < 4; i++)
            for (int j = 0; j < 4; j++) {
                float2 v = sS[i * 4 + j];
                M_[i][j] = make_float2((i == j ? 1.f : 0.f) - v.x, -v.y);
                M_[i][4 + j] = make_float2(i == j ? 1.f : 0.f, 0.f);
            }
        for (int col = 0; col < 4; col++) {
            float2 p = M_[col][col];
            float d = 1.f / (p.x * p.x + p.y * p.y);
            float2 pinv = make_float2(p.x * d, -p.y * d);
            for (int j = 0; j < 8; j++) M_[col][j] = cmulf(M_[col][j], pinv);
            for (int rr = 0; rr < 4; rr++)
                if (rr != col) {
                    float2 f = M_[rr][col];
                    for (int j = 0; j < 8; j++) {
                        float2 s = cmulf(f, M_[col][j]);
                        M_[rr][j].x -= s.x;
                        M_[rr][j].y -= s.y;
                    }
                }
        }
        for (int i = 0; i < 4; i++)
            for (int j = 0; j < 4; j++) sK[i * 4 + j] = M_[i][4 + j];
    }
    __syncthreads();

    // Da, U, V
    if (t < N) {
        float2 mv = sminv[t];
        g_Da[t] = make_float2(2.f * mv.x - 1.f, 2.f * mv.y);
        #pragma unroll
        for (int r = 0; r < RNK; r++) {
            float2 pk = make_float2(0.f, 0.f);
            #pragma unroll
            for (int s2 = 0; s2 < RNK; s2++) {
                float pv = P[t * RNK + s2];
                pk.x += pv * sK[s2 * 4 + r].x;
                pk.y += pv * sK[s2 * 4 + r].y;
            }
            float2 u = cmulf(make_float2(2.f * c * mv.x, 2.f * c * mv.y), pk);
            g_U[t * RNK + r] = u;
            float qv = Q[t * RNK + r];
            g_V[r * N + t] = make_float2(qv * mv.x, qv * mv.y);
        }
    }
    __syncthreads();

    // W[r][i] = sum_k V[r][k] * B[k][i]
    {
        int i = t;
        #pragma unroll
        for (int r = 0; r < RNK; r++) {
            float2 acc = make_float2(0.f, 0.f);
            for (int k = 0; k < N; k++) {
                float coef = Q[k * RNK + r] * Bm[k * DIN + i];
                acc.x += coef * sminv[k].x;
                acc.y += coef * sminv[k].y;
            }
            sW[r * DIN + i] = acc;
        }
    }
    __syncthreads();

    // B_d (transposed store)
    const float sq = sqrtf(DT_F);
    for (int idx = t; idx < N * DIN; idx += 128) {
        int j = idx >> 7, i = idx & 127;
        float2 mv = sminv[j];
        float bv = Bm[j * DIN + i];
        float2 acc = make_float2(bv * mv.x, bv * mv.y);
        #pragma unroll
        for (int r = 0; r < RNK; r++) {
            float2 u = g_U[j * RNK + r];
            acc = cfma(make_float2(0.5f * u.x, 0.5f * u.y), sW[r * DIN + i], acc);
        }
        g_Bd[i * N + j] = make_float2(sq * acc.x, sq * acc.y);
    }
    // dense A_d
    for (int idx = t; idx < N * N; idx += 128) {
        int j = idx >> 6, k = idx & 63;
        float2 acc = (j == k) ? g_Da[j] : make_float2(0.f, 0.f);
        #pragma unroll
        for (int r = 0; r < RNK; r++) acc = cfma(g_U[j * RNK + r], g_V[r * N + k], acc);
        g_Ad[j * N + k] = acc;
    }
    // transposes
    for (int idx = t; idx < DOUT * N; idx += 128) {
        int o = idx & 127, k = idx >> 7;
        g_CT[k * DOUT + o] = C[o * N + k];
    }
    for (int idx = t; idx < DOUT * DIN; idx += 128) {
        int o = idx & 127, k = idx >> 7;
        g_DT[k * DOUT + o] = D[o * DIN + k];
    }
    // D-zero flag
    {
        float s = 0.f;
        for (int i = t; i < DOUT * DIN; i += 128) s += fabsf(D[i]);
        sred[t] = s;
        __syncthreads();
        for (int st = 64; st > 0; st >>= 1) {
            if (t < st) sred[t] += sred[t + st];
            __syncthreads();
        }
        if (t == 0) g_dflag = (sred[0] != 0.f) ? 1 : 0;
    }
}

// ---------------- A_d^128 via 7 squarings inside ONE cluster kernel ----------------
// cluster of 8 CTAs, 128 threads each. Global ping-pong g_Ad <-> g_Atmp.
// Reads use ld.global.cg (L2) so inter-CTA visibility needs only membar.gpu + cluster barrier.
__global__ void __cluster_dims__(8, 1, 1) __launch_bounds__(128) power_kernel() {
    const int t = threadIdx.x;
    const int cr = blockIdx.x;           // cluster rank == block index (single cluster)
    const int row = cr * 8 + (t >> 4);   // 8 rows per CTA
    const int col = (t & 15) * 4;        // 4 consecutive cols per thread

    #pragma unroll 1
    for (int it = 0; it < 7; it++) {
        const float2* src = (it & 1) ? g_Atmp : g_Ad;
        float2*       dst = (it & 1) ? g_Ad : g_Atmp;
        float2 a0 = make_float2(0.f, 0.f), a1 = a0, a2 = a0, a3 = a0;
        #pragma unroll 8
        for (int k = 0; k < N; k++) {
            float2 av = __ldcg(&src[row * N + k]);
            const float4* bp = (const float4*)&src[k * N + col];
            float4 b01 = __ldcg(&bp[0]);
            float4 b23 = __ldcg(&bp[1]);
            a0 = cfma(av, make_float2(b01.x, b01.y), a0);
            a1 = cfma(av, make_float2(b01.z, b01.w), a1);
            a2 = cfma(av, make_float2(b23.x, b23.y), a2);
            a3 = cfma(av, make_float2(b23.z, b23.w), a3);
        }
        dst[row * N + col + 0] = a0;
        dst[row * N + col + 1] = a1;
        dst[row * N + col + 2] = a2;
        dst[row * N + col + 3] = a3;
        __threadfence();
        asm volatile("barrier.cluster.arrive.aligned;" ::: "memory");
        asm volatile("barrier.cluster.wait.aligned;" ::: "memory");
    }
    // after 7 iterations (last it=6 even): A^128 lives in g_Atmp
}

// ---------------- bu = u @ B_d^T  (complex out), packed f32x2 GEMM ----------------
__global__ __launch_bounds__(256) void bu_gemm_kernel(const float* __restrict__ u) {
    __shared__ float  su[32][129];
    __shared__ float2 sb[32][66];
    const int tid = threadIdx.x;
    const int tx = tid & 15, ty = tid >> 4;
    const size_t bt0 = (size_t)blockIdx.x * 128;

    unsigned long long acc[8][4];
    #pragma unroll
    for (int i = 0; i < 8; i++)
        #pragma unroll
        for (int j = 0; j < 4; j++) acc[i][j] = 0ull;

    for (int k0 = 0; k0 < DIN; k0 += 32) {
        #pragma unroll
        for (int l = 0; l < 4; l++) {
            int idx = tid + l * 256;
            int row = idx >> 3, k4 = idx & 7;
            float4 v = *(const float4*)&u[(bt0 + row) * DIN + k0 + k4 * 4];
            su[k4 * 4 + 0][row] = v.x;
            su[k4 * 4 + 1][row] = v.y;
            su[k4 * 4 + 2][row] = v.z;
            su[k4 * 4 + 3][row] = v.w;
        }
        #pragma unroll
        for (int l = 0; l < 4; l++) {
            int idx = tid + l * 256;
            int nn2 = idx & 31, kk = idx >> 5;
            float4 v = *(const float4*)&g_Bd[(k0 + kk) * N + nn2 * 2];
            *(float4*)&sb[kk][nn2 * 2] = v;
        }
        __syncthreads();
        #pragma unroll
        for (int k = 0; k < 32; k++) {
            unsigned long long a8[8], b4[4];
            #pragma unroll
            for (int i = 0; i < 8; i++) {
                float av = su[k][ty * 8 + i];
                a8[i] = pack2(av, av);
            }
            #pragma unroll
            for (int j = 0; j < 4; j++)
                b4[j] = *(const unsigned long long*)&sb[k][tx * 4 + j];
            #pragma unroll
            for (int i = 0; i < 8; i++)
                #pragma unroll
                for (int j = 0; j < 4; j++) acc[i][j] = ffma2(a8[i], b4[j], acc[i][j]);
        }
        __syncthreads();
    }
    #pragma unroll
    for (int i = 0; i < 8; i++) {
        #pragma unroll
        for (int jj = 0; jj < 2; jj++) {
            float2 lo = unpack2(acc[i][2 * jj]);
            float2 hi = unpack2(acc[i][2 * jj + 1]);
            float4 v = make_float4(lo.x, lo.y, hi.x, hi.y);
            *(float4*)&g_bu[(bt0 + ty * 8 + i) * N + tx * 4 + 2 * jj] = v;
        }
    }
}

// ---------------- chunked scan, f32x2-packed across the (ln, ln+32) state pair ----------------
// mode 0: local sums from zero -> g_csum ; mode 1: final pass from g_xin -> g_xr
__global__ __launch_bounds__(128) void scan_kernel(int mode) {
    const int w  = blockIdx.x * 4 + (threadIdx.x >> 5);   // 0..2047
    const int ln = threadIdx.x & 31;
    const int b = w >> 6;
    const int g = w & 63;
    const size_t bt0 = (size_t)b * T + (size_t)g * L;
    typedef unsigned long long ull;

    // packed constants: slot.lo = state ln, slot.hi = state ln+32
    float2 Da0 = g_Da[ln], Da1 = g_Da[ln + 32];
    ull da_r  = pack2(Da0.x, Da1.x);
    ull da_i  = pack2(Da0.y, Da1.y);
    ull da_iN = pack2(-Da0.y, -Da1.y);
    ull ur[RNK], ui[RNK], uiN[RNK], vr[RNK], vi[RNK], viN[RNK];
    #pragma unroll
    for (int r = 0; r < RNK; r++) {
        float2 U0 = g_U[ln * RNK + r], U1 = g_U[(ln + 32) * RNK + r];
        float2 V0 = g_V[r * N + ln],   V1 = g_V[r * N + ln + 32];
        ur[r]  = pack2(U0.x, U1.x);
        ui[r]  = pack2(U0.y, U1.y);
        uiN[r] = pack2(-U0.y, -U1.y);
        vr[r]  = pack2(V0.x, V1.x);
        vi[r]  = pack2(V0.y, V1.y);
        viN[r] = pack2(-V0.y, -V1.y);
    }

    ull xr = 0ull, xi = 0ull;
    if (mode) {
        int ci = (b * G + g) * N;
        float2 x0 = g_xin[ci + ln], x1 = g_xin[ci + ln + 32];
        xr = pack2(x0.x, x1.x);
        xi = pack2(x0.y, x1.y);
    }

    const float2* bup = g_bu + bt0 * N;
    float2 pb0[PF], pb1[PF];
    #pragma unroll
    for (int j = 0; j < PF; j++) {
        pb0[j] = bup[j * N + ln];
        pb1[j] = bup[j * N + ln + 32];
    }

    const ull zero = 0ull;
    for (int t = 0; t < L; t++) {
        float2 c0 = pb0[t & (PF - 1)], c1 = pb1[t & (PF - 1)];
        int tp = t + PF;
        if (tp < L) {
            pb0[t & (PF - 1)] = bup[tp * N + ln];
            pb1[t & (PF - 1)] = bup[tp * N + ln + 32];
        }
        // rank partials  s[r] = sum_n V[r][n] x[n]
        float sre[RNK], sim[RNK];
        #pragma unroll
        for (int r = 0; r < RNK; r++) {
            ull pr = ffma2(viN[r], xi, ffma2(vr[r], xr, zero));
            ull pi = ffma2(vi[r],  xr, ffma2(vr[r], xi, zero));
            float2 a = unpack2(pr);
            float2 bb = unpack2(pi);
            sre[r] = a.x + a.y;
            sim[r] = bb.x + bb.y;
        }
        #pragma unroll
        for (int off = 16; off > 0; off >>= 1) {
            #pragma unroll
            for (int r = 0; r < RNK; r++) {
                sre[r] += __shfl_xor_sync(0xffffffffu, sre[r], off);
                sim[r] += __shfl_xor_sync(0xffffffffu, sim[r], off);
            }
        }
        ull bur = pack2(c0.x, c1.x);
        ull bui = pack2(c0.y, c1.y);
        ull yr = ffma2(da_r, xr, ffma2(da_iN, xi, bur));
        ull yi = ffma2(da_r, xi, ffma2(da_i,  xr, bui));
        #pragma unroll
        for (int r = 0; r < RNK; r++) {
            ull pr = pack2(sre[r], sre[r]);
            ull pi = pack2(sim[r], sim[r]);
            yr = ffma2(uiN[r], pi, ffma2(ur[r], pr, yr));
            yi = ffma2(ui[r],  pr, ffma2(ur[r], pi, yi));
        }
        xr = yr;
        xi = yi;
        if (mode) {
            float2 o = unpack2(xr);
            g_xr[(bt0 + t) * N + ln]      = o.x;
            g_xr[(bt0 + t) * N + ln + 32] = o.y;
        }
    }
    if (!mode) {
        int ci = (b * G + g) * N;
        float2 rr = unpack2(xr), i2 = unpack2(xi);
        g_csum[ci + ln]      = make_float2(rr.x, i2.x);
        g_csum[ci + ln + 32] = make_float2(rr.y, i2.y);
    }
}

// ---------------- chunk-level chain: x_in[g+1] = A^L x_in[g] + c_g ----------------
__global__ __launch_bounds__(64) void chain_kernel() {
    __shared__ float2 sA[N * 65];
    __shared__ float2 sx[N];
    const int b = blockIdx.x, t = threadIdx.x;
    for (int i = t; i < N * N; i += 64) {
        int r = i >> 6, c = i & 63;
        sA[r * 65 + c] = g_Atmp[i];   // A^128
    }
    float2 x = make_float2(0.f, 0.f);
    for (int g = 0; g < G; g++) {
        int ci = (b * G + g) * N;
        g_xin[ci + t] = x;
        sx[t] = x;
        __syncthreads();
        float2 a0 = g_csum[ci + t];
        float2 a1 = make_float2(0.f, 0.f), a2 = a1, a3 = a1;
        #pragma unroll 4
        for (int k = 0; k < N; k += 4) {
            a0 = cfma(sA[t * 65 + k + 0], sx[k + 0], a0);
            a1 = cfma(sA[t * 65 + k + 1], sx[k + 1], a1);
            a2 = cfma(sA[t * 65 + k + 2], sx[k + 2], a2);
            a3 = cfma(sA[t * 65 + k + 3], sx[k + 3], a3);
        }
        x.x = (a0.x + a1.x) + (a2.x + a3.x);
        x.y = (a0.y + a1.y) + (a2.y + a3.y);
        __syncthreads();
    }
}

// ---------------- y = Re(x) @ C^T (+ u @ D^T if D != 0), packed f32x2 GEMM ----------------
__global__ __launch_bounds__(256) void y_gemm_kernel(const float* __restrict__ u,
                                                     float* __restrict__ out) {
    __shared__ float sx[32][129];
    __shared__ float sc[32][132];
    const int tid = threadIdx.x;
    const int tx = tid & 15, ty = tid >> 4;
    const size_t bt0 = (size_t)blockIdx.x * 128;

    unsigned long long acc[8][4];
    #pragma unroll
    for (int i = 0; i < 8; i++)
        #pragma unroll
        for (int j = 0; j < 4; j++) acc[i][j] = 0ull;

    for (int k0 = 0; k0 < N; k0 += 32) {
        #pragma unroll
        for (int l = 0; l < 4; l++) {
            int idx = tid + l * 256;
            int row = idx >> 3, k4 = idx & 7;
            float4 v = *(const float4*)&g_xr[(bt0 + row) * N + k0 + k4 * 4];
            sx[k4 * 4 + 0][row] = v.x;
            sx[k4 * 4 + 1][row] = v.y;
            sx[k4 * 4 + 2][row] = v.z;
            sx[k4 * 4 + 3][row] = v.w;
        }
        #pragma unroll
        for (int l = 0; l < 4; l++) {
            int idx = tid + l * 256;
            int o4 = idx & 31, kk = idx >> 5;
            float4 v = *(const float4*)&g_CT[(k0 + kk) * DOUT + o4 * 4];
            *(float4*)&sc[kk][o4 * 4] = v;
        }
        __syncthreads();
        #pragma unroll
        for (int k = 0; k < 32; k++) {
            unsigned long long a8[8], b4[4];
            #pragma unroll
            for (int i = 0; i < 8; i++) {
                float av = sx[k][ty * 8 + i];
                a8[i] = pack2(av, av);
            }
            #pragma unroll
            for (int j = 0; j < 4; j++)
                b4[j] = *(const unsigned long long*)&sc[k][tx * 8 + 2 * j];
            #pragma unroll
            for (int i = 0; i < 8; i++)
                #pragma unroll
                for (int j = 0; j < 4; j++) acc[i][j] = ffma2(a8[i], b4[j], acc[i][j]);
        }
        __syncthreads();
    }
    if (g_dflag) {
        for (int k0 = 0; k0 < DIN; k0 += 32) {
            #pragma unroll
            for (int l = 0; l < 4; l++) {
                int idx = tid + l * 256;
                int row = idx >> 3, k4 = idx & 7;
                float4 v = *(const float4*)&u[(bt0 + row) * DIN + k0 + k4 * 4];
                sx[k4 * 4 + 0][row] = v.x;
                sx[k4 * 4 + 1][row] = v.y;
                sx[k4 * 4 + 2][row] = v.z;
                sx[k4 * 4 + 3][row] = v.w;
            }
            #pragma unroll
            for (int l = 0; l < 4; l++) {
                int idx = tid + l * 256;
                int o4 = idx & 31, kk = idx >> 5;
                float4 v = *(const float4*)&g_DT[(k0 + kk) * DOUT + o4 * 4];
                *(float4*)&sc[kk][o4 * 4] = v;
            }
            __syncthreads();
            #pragma unroll
            for (int k = 0; k < 32; k++) {
                unsigned long long a8[8], b4[4];
                #pragma unroll
                for (int i = 0; i < 8; i++) {
                    float av = sx[k][ty * 8 + i];
                    a8[i] = pack2(av, av);
                }
                #pragma unroll
                for (int j = 0; j < 4; j++)
                    b4[j] = *(const unsigned long long*)&sc[k][tx * 8 + 2 * j];
                #pragma unroll
                for (int i = 0; i < 8; i++)
                    #pragma unroll
                    for (int j = 0; j < 4; j++) acc[i][j] = ffma2(a8[i], b4[j], acc[i][j]);
            }
            __syncthreads();
        }
    }
    #pragma unroll
    for (int i = 0; i < 8; i++) {
        float2 p0 = unpack2(acc[i][0]);
        float2 p1 = unpack2(acc[i][1]);
        float2 p2 = unpack2(acc[i][2]);
        float2 p3 = unpack2(acc[i][3]);
        float4 v0 = make_float4(p0.x, p0.y, p1.x, p1.y);
        float4 v1 = make_float4(p2.x, p2.y, p3.x, p3.y);
        size_t base = (bt0 + ty * 8 + i) * DOUT + tx * 8;
        *(float4*)&out[base]     = v0;
        *(float4*)&out[base + 4] = v1;
    }
}

// ---------------- launch ----------------
extern "C" void kernel_launch(void* const* d_in, const int* in_sizes, int n_in,
                              void* d_out, int out_size) {
    const float* u  = (const float*)d_in[0];
    const float* lw = (const float*)d_in[1];
    const float* zl = (const float*)d_in[2];
    const float* P  = (const float*)d_in[3];
    const float* Q  = (const float*)d_in[4];
    const float* Bm = (const float*)d_in[5];
    const float* C  = (const float*)d_in[6];
    const float* D  = (const float*)d_in[7];
    float* out = (float*)d_out;

    setup_kernel<<<1, 128>>>(lw, zl, P, Q, Bm, C, D);
    power_kernel<<<8, 128>>>();                 // A_d^128 -> g_Atmp (one cluster launch)
    bu_gemm_kernel<<<BT / 128, 256>>>(u);
    scan_kernel<<<(BATCH * G) / 4, 128>>>(0);   // local chunk sums
    chain_kernel<<<BATCH, 64>>>();              // chunk-level recurrence
    scan_kernel<<<(BATCH * G) / 4, 128>>>(1);   // final pass, store Re(x)
    y_gemm_kernel<<<BT / 128, 256>>>(u, out);
}

// round 5
// speedup vs baseline: 1.0034x; 1.0034x over previous
#include <cuda_runtime.h>

// ---------------- problem constants ----------------
#define DT_F 0.01f
constexpr int N    = 64;     // state dim
constexpr int RNK  = 4;      // low rank
constexpr int DIN  = 128;
constexpr int DOUT = 128;
constexpr int BATCH = 32;
constexpr int T    = 8192;
constexpr int L    = 128;            // chunk length
constexpr int G    = T / L;          // 64 chunks
constexpr int BT   = BATCH * T;      // 262144
constexpr int PF   = 8;              // scan prefetch depth

// ---------------- device scratch (static, no allocs) ----------------
__device__ float2 g_bu[(size_t)BT * N];      // 128 MB : B_d @ u  (complex)
__device__ float  g_xr[(size_t)BT * N];      // 64 MB  : Re(x_t)
__device__ float2 g_Bd[DIN * N];             // B_d transposed: [i][n]
__device__ float2 g_Da[N];
__device__ float2 g_U[N * RNK];
__device__ float2 g_V[RNK * N];
__device__ float2 g_Ad[N * N];
__device__ float2 g_Atmp[N * N];
__device__ float2 g_csum[BATCH * G * N];
__device__ float2 g_xin[BATCH * G * N];
__device__ float  g_CT[N * DOUT];            // C transposed: [k][o]
__device__ float  g_DT[DIN * DOUT];          // D transposed: [k][o]
__device__ int    g_dflag;

// ---------------- helpers ----------------
__device__ __forceinline__ float2 cfma(float2 a, float2 b, float2 c) { // c + a*b
    float2 r;
    r.x = fmaf(a.x, b.x, fmaf(-a.y, b.y, c.x));
    r.y = fmaf(a.x, b.y, fmaf( a.y, b.x, c.y));
    return r;
}
__device__ __forceinline__ float2 cmulf(float2 a, float2 b) {
    return cfma(a, b, make_float2(0.f, 0.f));
}
__device__ __forceinline__ unsigned long long ffma2(unsigned long long a,
                                                    unsigned long long b,
                                                    unsigned long long c) {
    unsigned long long d;
    asm("fma.rn.f32x2 %0, %1, %2, %3;" : "=l"(d) : "l"(a), "l"(b), "l"(c));
    return d;
}
__device__ __forceinline__ unsigned long long pack2(float x, float y) {
    unsigned long long r;
    asm("mov.b64 %0, {%1, %2};" : "=l"(r) : "f"(x), "f"(y));
    return r;
}
__device__ __forceinline__ float2 unpack2(unsigned long long v) {
    float x, y;
    asm("mov.b64 {%0, %1}, %2;" : "=f"(x), "=f"(y) : "l"(v));
    return make_float2(x, y);
}

// ---------------- setup: Woodbury factors, B_d, dense A_d, transposes, dflag ----------------
__global__ void setup_kernel(const float* __restrict__ lw, const float* __restrict__ zl,
                             const float* __restrict__ P,  const float* __restrict__ Q,
                             const float* __restrict__ Bm, const float* __restrict__ C,
                             const float* __restrict__ D) {
    __shared__ float2 sminv[N];
    __shared__ float2 sS[16];
    __shared__ float2 sK[16];
    __shared__ float2 sW[RNK * DIN];
    __shared__ float  sred[128];
    const float c = 0.5f * DT_F;
    const int t = threadIdx.x;   // 128 threads

    if (t < N) {
        float om = expf(lw[t]);
        float ze = 1.f / (1.f + expf(-zl[t]));
        float lr = -ze * om;
        float li = om * sqrtf(fmaxf(1.f - ze * ze, 1e-8f));
        float mr = 1.f - c * lr;
        float mi = -c * li;
        float inv = 1.f / (mr * mr + mi * mi);
        sminv[t] = make_float2(mr * inv, -mi * inv);
    }
    __syncthreads();

    // S = c * Q^T Minv P  (4x4 complex)
    if (t < 16) {
        int r = t >> 2, s2 = t & 3;
        float2 acc = make_float2(0.f, 0.f);
        for (int k = 0; k < N; k++) {
            float coef = Q[k * RNK + r] * P[k * RNK + s2];
            acc.x += coef * sminv[k].x;
            acc.y += coef * sminv[k].y;
        }
        sS[t] = make_float2(c * acc.x, c * acc.y);
    }
    __syncthreads();

    // K = inv(I4 - S), Gauss-Jordan
    if (t == 0) {
        float2 M_[4][8];
        for (int i = 0; i < 4; i++)
            for (int j = 0; j < 4; j++) {
                float2 v = sS[i * 4 + j];
                M_[i][j] = make_float2((i == j ? 1.f : 0.f) - v.x, -v.y);
                M_[i][4 + j] = make_float2(i == j ? 1.f : 0.f, 0.f);
            }
        for (int col = 0; col < 4; col++) {
            float2 p = M_[col][col];
            float d = 1.f / (p.x * p.x + p.y * p.y);
            float2 pinv = make_float2(p.x * d, -p.y * d);
            for (int j = 0; j < 8; j++) M_[col][j] = cmulf(M_[col][j], pinv);
            for (int rr = 0; rr < 4; rr++)
                if (rr != col) {
                    float2 f = M_[rr][col];
                    for (int j = 0; j < 8; j++) {
                        float2 s = cmulf(f, M_[col][j]);
                        M_[rr][j].x -= s.x;
                        M_[rr][j].y -= s.y;
                    }
                }
        }
        for (int i = 0; i < 4; i++)
            for (int j = 0; j < 4; j++) sK[i * 4 + j] = M_[i][4 + j];
    }
    __syncthreads();

    // Da, U, V
    if (t < N) {
        float2 mv = sminv[t];
        g_Da[t] = make_float2(2.f * mv.x - 1.f, 2.f * mv.y);
        #pragma unroll
        for (int r = 0; r < RNK; r++) {
            float2 pk = make_float2(0.f, 0.f);
            #pragma unroll
            for (int s2 = 0; s2 < RNK; s2++) {
                float pv = P[t * RNK + s2];
                pk.x += pv * sK[s2 * 4 + r].x;
                pk.y += pv * sK[s2 * 4 + r].y;
            }
            float2 u = cmulf(make_float2(2.f * c * mv.x, 2.f * c * mv.y), pk);
            g_U[t * RNK + r] = u;
            float qv = Q[t * RNK + r];
            g_V[r * N + t] = make_float2(qv * mv.x, qv * mv.y);
        }
    }
    __syncthreads();

    // W[r][i] = sum_k V[r][k] * B[k][i]
    {
        int i = t;
        #pragma unroll
        for (int r = 0; r < RNK; r++) {
            float2 acc = make_float2(0.f, 0.f);
            for (int k = 0; k < N; k++) {
                float coef = Q[k * RNK + r] * Bm[k * DIN + i];
                acc.x += coef * sminv[k].x;
                acc.y += coef * sminv[k].y;
            }
            sW[r * DIN + i] = acc;
        }
    }
    __syncthreads();

    // B_d (transposed store)
    const float sq = sqrtf(DT_F);
    for (int idx = t; idx < N * DIN; idx += 128) {
        int j = idx >> 7, i = idx & 127;
        float2 mv = sminv[j];
        float bv = Bm[j * DIN + i];
        float2 acc = make_float2(bv * mv.x, bv * mv.y);
        #pragma unroll
        for (int r = 0; r < RNK; r++) {
            float2 u = g_U[j * RNK + r];
            acc = cfma(make_float2(0.5f * u.x, 0.5f * u.y), sW[r * DIN + i], acc);
        }
        g_Bd[i * N + j] = make_float2(sq * acc.x, sq * acc.y);
    }
    // dense A_d
    for (int idx = t; idx < N * N; idx += 128) {
        int j = idx >> 6, k = idx & 63;
        float2 acc = (j == k) ? g_Da[j] : make_float2(0.f, 0.f);
        #pragma unroll
        for (int r = 0; r < RNK; r++) acc = cfma(g_U[j * RNK + r], g_V[r * N + k], acc);
        g_Ad[j * N + k] = acc;
    }
    // transposes
    for (int idx = t; idx < DOUT * N; idx += 128) {
        int o = idx & 127, k = idx >> 7;
        g_CT[k * DOUT + o] = C[o * N + k];
    }
    for (int idx = t; idx < DOUT * DIN; idx += 128) {
        int o = idx & 127, k = idx >> 7;
        g_DT[k * DOUT + o] = D[o * DIN + k];
    }
    // D-zero flag
    {
        float s = 0.f;
        for (int i = t; i < DOUT * DIN; i += 128) s += fabsf(D[i]);
        sred[t] = s;
        __syncthreads();
        for (int st = 64; st > 0; st >>= 1) {
            if (t < st) sred[t] += sred[t + st];
            __syncthreads();
        }
        if (t == 0) g_dflag = (sred[0] != 0.f) ? 1 : 0;
    }
}

// ---------------- A_d^128 via 7 squarings inside ONE cluster kernel ----------------
// cluster of 8 CTAs, 128 threads each. Global ping-pong g_Ad <-> g_Atmp.
// Reads use ld.global.cg (L2) so inter-CTA visibility needs only membar.gpu + cluster barrier.
__global__ void __cluster_dims__(8, 1, 1) __launch_bounds__(128) power_kernel() {
    const int t = threadIdx.x;
    const int cr = blockIdx.x;           // cluster rank == block index (single cluster)
    const int row = cr * 8 + (t >> 4);   // 8 rows per CTA
    const int col = (t & 15) * 4;        // 4 consecutive cols per thread

    #pragma unroll 1
    for (int it = 0; it < 7; it++) {
        const float2* src = (it & 1) ? g_Atmp : g_Ad;
        float2*       dst = (it & 1) ? g_Ad : g_Atmp;
        float2 a0 = make_float2(0.f, 0.f), a1 = a0, a2 = a0, a3 = a0;
        #pragma unroll 8
        for (int k = 0; k < N; k++) {
            float2 av = __ldcg(&src[row * N + k]);
            const float4* bp = (const float4*)&src[k * N + col];
            float4 b01 = __ldcg(&bp[0]);
            float4 b23 = __ldcg(&bp[1]);
            a0 = cfma(av, make_float2(b01.x, b01.y), a0);
            a1 = cfma(av, make_float2(b01.z, b01.w), a1);
            a2 = cfma(av, make_float2(b23.x, b23.y), a2);
            a3 = cfma(av, make_float2(b23.z, b23.w), a3);
        }
        dst[row * N + col + 0] = a0;
        dst[row * N + col + 1] = a1;
        dst[row * N + col + 2] = a2;
        dst[row * N + col + 3] = a3;
        __threadfence();
        asm volatile("barrier.cluster.arrive.aligned;" ::: "memory");
        asm volatile("barrier.cluster.wait.aligned;" ::: "memory");
    }
    // after 7 iterations (last it=6 even): A^128 lives in g_Atmp
}

// ---------------- bu = u @ B_d^T  (complex out), packed f32x2 GEMM ----------------
__global__ __launch_bounds__(256) void bu_gemm_kernel(const float* __restrict__ u) {
    __shared__ float  su[32][129];
    __shared__ float2 sb[32][66];
    const int tid = threadIdx.x;
    const int tx = tid & 15, ty = tid >> 4;
    const size_t bt0 = (size_t)blockIdx.x * 128;

    unsigned long long acc[8][4];
    #pragma unroll
    for (int i = 0; i < 8; i++)
        #pragma unroll
        for (int j = 0; j < 4; j++) acc[i][j] = 0ull;

    for (int k0 = 0; k0 < DIN; k0 += 32) {
        #pragma unroll
        for (int l = 0; l < 4; l++) {
            int idx = tid + l * 256;
            int row = idx >> 3, k4 = idx & 7;
            float4 v = *(const float4*)&u[(bt0 + row) * DIN + k0 + k4 * 4];
            su[k4 * 4 + 0][row] = v.x;
            su[k4 * 4 + 1][row] = v.y;
            su[k4 * 4 + 2][row] = v.z;
            su[k4 * 4 + 3][row] = v.w;
        }
        #pragma unroll
        for (int l = 0; l < 4; l++) {
            int idx = tid + l * 256;
            int nn2 = idx & 31, kk = idx >> 5;
            float4 v = *(const float4*)&g_Bd[(k0 + kk) * N + nn2 * 2];
            *(float4*)&sb[kk][nn2 * 2] = v;
        }
        __syncthreads();
        #pragma unroll
        for (int k = 0; k < 32; k++) {
            unsigned long long a8[8], b4[4];
            #pragma unroll
            for (int i = 0; i < 8; i++) {
                float av = su[k][ty * 8 + i];
                a8[i] = pack2(av, av);
            }
            #pragma unroll
            for (int j = 0; j < 4; j++)
                b4[j] = *(const unsigned long long*)&sb[k][tx * 4 + j];
            #pragma unroll
            for (int i = 0; i < 8; i++)
                #pragma unroll
                for (int j = 0; j < 4; j++) acc[i][j] = ffma2(a8[i], b4[j], acc[i][j]);
        }
        __syncthreads();
    }
    #pragma unroll
    for (int i = 0; i < 8; i++) {
        #pragma unroll
        for (int jj = 0; jj < 2; jj++) {
            float2 lo = unpack2(acc[i][2 * jj]);
            float2 hi = unpack2(acc[i][2 * jj + 1]);
            float4 v = make_float4(lo.x, lo.y, hi.x, hi.y);
            *(float4*)&g_bu[(bt0 + ty * 8 + i) * N + tx * 4 + 2 * jj] = v;
        }
    }
}

// ---------------- chunked scan, f32x2-packed across the (ln, ln+32) state pair ----------------
// mode 0: local sums from zero -> g_csum ; mode 1: final pass from g_xin -> g_xr
__global__ __launch_bounds__(128) void scan_kernel(int mode) {
    const int w  = blockIdx.x * 4 + (threadIdx.x >> 5);   // 0..2047
    const int ln = threadIdx.x & 31;
    const int b = w >> 6;
    const int g = w & 63;
    const size_t bt0 = (size_t)b * T + (size_t)g * L;
    typedef unsigned long long ull;

    // packed constants: slot.lo = state ln, slot.hi = state ln+32
    float2 Da0 = g_Da[ln], Da1 = g_Da[ln + 32];
    ull da_r  = pack2(Da0.x, Da1.x);
    ull da_i  = pack2(Da0.y, Da1.y);
    ull da_iN = pack2(-Da0.y, -Da1.y);
    ull ur[RNK], ui[RNK], uiN[RNK], vr[RNK], vi[RNK], viN[RNK];
    #pragma unroll
    for (int r = 0; r < RNK; r++) {
        float2 U0 = g_U[ln * RNK + r], U1 = g_U[(ln + 32) * RNK + r];
        float2 V0 = g_V[r * N + ln],   V1 = g_V[r * N + ln + 32];
        ur[r]  = pack2(U0.x, U1.x);
        ui[r]  = pack2(U0.y, U1.y);
        uiN[r] = pack2(-U0.y, -U1.y);
        vr[r]  = pack2(V0.x, V1.x);
        vi[r]  = pack2(V0.y, V1.y);
        viN[r] = pack2(-V0.y, -V1.y);
    }

    ull xr = 0ull, xi = 0ull;
    if (mode) {
        int ci = (b * G + g) * N;
        float2 x0 = g_xin[ci + ln], x1 = g_xin[ci + ln + 32];
        xr = pack2(x0.x, x1.x);
        xi = pack2(x0.y, x1.y);
    }

    const float2* bup = g_bu + bt0 * N;
    float2 pb0[PF], pb1[PF];
    #pragma unroll
    for (int j = 0; j < PF; j++) {
        pb0[j] = bup[j * N + ln];
        pb1[j] = bup[j * N + ln + 32];
    }

    const ull zero = 0ull;
    for (int t = 0; t < L; t++) {
        float2 c0 = pb0[t & (PF - 1)], c1 = pb1[t & (PF - 1)];
        int tp = t + PF;
        if (tp < L) {
            pb0[t & (PF - 1)] = bup[tp * N + ln];
            pb1[t & (PF - 1)] = bup[tp * N + ln + 32];
        }
        // rank partials  s[r] = sum_n V[r][n] x[n]
        float sre[RNK], sim[RNK];
        #pragma unroll
        for (int r = 0; r < RNK; r++) {
            ull pr = ffma2(viN[r], xi, ffma2(vr[r], xr, zero));
            ull pi = ffma2(vi[r],  xr, ffma2(vr[r], xi, zero));
            float2 a = unpack2(pr);
            float2 bb = unpack2(pi);
            sre[r] = a.x + a.y;
            sim[r] = bb.x + bb.y;
        }
        #pragma unroll
        for (int off = 16; off > 0; off >>= 1) {
            #pragma unroll
            for (int r = 0; r < RNK; r++) {
                sre[r] += __shfl_xor_sync(0xffffffffu, sre[r], off);
                sim[r] += __shfl_xor_sync(0xffffffffu, sim[r], off);
            }
        }
        ull bur = pack2(c0.x, c1.x);
        ull bui = pack2(c0.y, c1.y);
        ull yr = ffma2(da_r, xr, ffma2(da_iN, xi, bur));
        ull yi = ffma2(da_r, xi, ffma2(da_i,  xr, bui));
        #pragma unroll
        for (int r = 0; r < RNK; r++) {
            ull pr = pack2(sre[r], sre[r]);
            ull pi = pack2(sim[r], sim[r]);
            yr = ffma2(uiN[r], pi, ffma2(ur[r], pr, yr));
            yi = ffma2(ui[r],  pr, ffma2(ur[r], pi, yi));
        }
        xr = yr;
        xi = yi;
        if (mode) {
            float2 o = unpack2(xr);
            g_xr[(bt0 + t) * N + ln]      = o.x;
            g_xr[(bt0 + t) * N + ln + 32] = o.y;
        }
    }
    if (!mode) {
        int ci = (b * G + g) * N;
        float2 rr = unpack2(xr), i2 = unpack2(xi);
        g_csum[ci + ln]      = make_float2(rr.x, i2.x);
        g_csum[ci + ln + 32] = make_float2(rr.y, i2.y);
    }
}

// ---------------- chunk-level chain: x_in[g+1] = A^L x_in[g] + c_g ----------------
__global__ __launch_bounds__(64) void chain_kernel() {
    __shared__ float2 sA[N * 65];
    __shared__ float2 sx[N];
    const int b = blockIdx.x, t = threadIdx.x;
    for (int i = t; i < N * N; i += 64) {
        int r = i >> 6, c = i & 63;
        sA[r * 65 + c] = g_Atmp[i];   // A^128
    }
    float2 x = make_float2(0.f, 0.f);
    for (int g = 0; g < G; g++) {
        int ci = (b * G + g) * N;
        g_xin[ci + t] = x;
        sx[t] = x;
        __syncthreads();
        float2 a0 = g_csum[ci + t];
        float2 a1 = make_float2(0.f, 0.f), a2 = a1, a3 = a1;
        #pragma unroll 4
        for (int k = 0; k < N; k += 4) {
            a0 = cfma(sA[t * 65 + k + 0], sx[k + 0], a0);
            a1 = cfma(sA[t * 65 + k + 1], sx[k + 1], a1);
            a2 = cfma(sA[t * 65 + k + 2], sx[k + 2], a2);
            a3 = cfma(sA[t * 65 + k + 3], sx[k + 3], a3);
        }
        x.x = (a0.x + a1.x) + (a2.x + a3.x);
        x.y = (a0.y + a1.y) + (a2.y + a3.y);
        __syncthreads();
    }
}

// ---------------- y = Re(x) @ C^T (+ u @ D^T if D != 0), packed f32x2 GEMM ----------------
__global__ __launch_bounds__(256) void y_gemm_kernel(const float* __restrict__ u,
                                                     float* __restrict__ out) {
    __shared__ float sx[32][129];
    __shared__ float sc[32][132];
    const int tid = threadIdx.x;
    const int tx = tid & 15, ty = tid >> 4;
    const size_t bt0 = (size_t)blockIdx.x * 128;

    unsigned long long acc[8][4];
    #pragma unroll
    for (int i = 0; i < 8; i++)
        #pragma unroll
        for (int j = 0; j < 4; j++) acc[i][j] = 0ull;

    for (int k0 = 0; k0 < N; k0 += 32) {
        #pragma unroll
        for (int l = 0; l < 4; l++) {
            int idx = tid + l * 256;
            int row = idx >> 3, k4 = idx & 7;
            float4 v = *(const float4*)&g_xr[(bt0 + row) * N + k0 + k4 * 4];
            sx[k4 * 4 + 0][row] = v.x;
            sx[k4 * 4 + 1][row] = v.y;
            sx[k4 * 4 + 2][row] = v.z;
            sx[k4 * 4 + 3][row] = v.w;
        }
        #pragma unroll
        for (int l = 0; l < 4; l++) {
            int idx = tid + l * 256;
            int o4 = idx & 31, kk = idx >> 5;
            float4 v = *(const float4*)&g_CT[(k0 + kk) * DOUT + o4 * 4];
            *(float4*)&sc[kk][o4 * 4] = v;
        }
        __syncthreads();
        #pragma unroll
        for (int k = 0; k < 32; k++) {
            unsigned long long a8[8], b4[4];
            #pragma unroll
            for (int i = 0; i < 8; i++) {
                float av = sx[k][ty * 8 + i];
                a8[i] = pack2(av, av);
            }
            #pragma unroll
            for (int j = 0; j < 4; j++)
                b4[j] = *(const unsigned long long*)&sc[k][tx * 8 + 2 * j];
            #pragma unroll
            for (int i = 0; i < 8; i++)
                #pragma unroll
                for (int j = 0; j < 4; j++) acc[i][j] = ffma2(a8[i], b4[j], acc[i][j]);
        }
        __syncthreads();
    }
    if (g_dflag) {
        for (int k0 = 0; k0 < DIN; k0 += 32) {
            #pragma unroll
            for (int l = 0; l < 4; l++) {
                int idx = tid + l * 256;
                int row = idx >> 3, k4 = idx & 7;
                float4 v = *(const float4*)&u[(bt0 + row) * DIN + k0 + k4 * 4];
                sx[k4 * 4 + 0][row] = v.x;
                sx[k4 * 4 + 1][row] = v.y;
                sx[k4 * 4 + 2][row] = v.z;
                sx[k4 * 4 + 3][row] = v.w;
            }
            #pragma unroll
            for (int l = 0; l < 4; l++) {
                int idx = tid + l * 256;
                int o4 = idx & 31, kk = idx >> 5;
                float4 v = *(const float4*)&g_DT[(k0 + kk) * DOUT + o4 * 4];
                *(float4*)&sc[kk][o4 * 4] = v;
            }
            __syncthreads();
            #pragma unroll
            for (int k = 0; k < 32; k++) {
                unsigned long long a8[8], b4[4];
                #pragma unroll
                for (int i = 0; i < 8; i++) {
                    float av = sx[k][ty * 8 + i];
                    a8[i] = pack2(av, av);
                }
                #pragma unroll
                for (int j = 0; j < 4; j++)
                    b4[j] = *(const unsigned long long*)&sc[k][tx * 8 + 2 * j];
                #pragma unroll
                for (int i = 0; i < 8; i++)
                    #pragma unroll
                    for (int j = 0; j < 4; j++) acc[i][j] = ffma2(a8[i], b4[j], acc[i][j]);
            }
            __syncthreads();
        }
    }
    #pragma unroll
    for (int i = 0; i < 8; i++) {
        float2 p0 = unpack2(acc[i][0]);
        float2 p1 = unpack2(acc[i][1]);
        float2 p2 = unpack2(acc[i][2]);
        float2 p3 = unpack2(acc[i][3]);
        float4 v0 = make_float4(p0.x, p0.y, p1.x, p1.y);
        float4 v1 = make_float4(p2.x, p2.y, p3.x, p3.y);
        size_t base = (bt0 + ty * 8 + i) * DOUT + tx * 8;
        *(float4*)&out[base]     = v0;
        *(float4*)&out[base + 4] = v1;
    }
}

// ---------------- launch ----------------
extern "C" void kernel_launch(void* const* d_in, const int* in_sizes, int n_in,
                              void* d_out, int out_size) {
    const float* u  = (const float*)d_in[0];
    const float* lw = (const float*)d_in[1];
    const float* zl = (const float*)d_in[2];
    const float* P  = (const float*)d_in[3];
    const float* Q  = (const float*)d_in[4];
    const float* Bm = (const float*)d_in[5];
    const float* C  = (const float*)d_in[6];
    const float* D  = (const float*)d_in[7];
    float* out = (float*)d_out;

    setup_kernel<<<1, 128>>>(lw, zl, P, Q, Bm, C, D);
    power_kernel<<<8, 128>>>();                 // A_d^128 -> g_Atmp (one cluster launch)
    bu_gemm_kernel<<<BT / 128, 256>>>(u);
    scan_kernel<<<(BATCH * G) / 4, 128>>>(0);   // local chunk sums
    chain_kernel<<<BATCH, 64>>>();              // chunk-level recurrence
    scan_kernel<<<(BATCH * G) / 4, 128>>>(1);   // final pass, store Re(x)
    y_gemm_kernel<<<BT / 128, 256>>>(u, out);
}

// round 7
// speedup vs baseline: 1.1593x; 1.1553x over previous
#include <cuda_runtime.h>

// ---------------- problem constants ----------------
#define DT_F 0.01f
constexpr int N    = 64;     // state dim
constexpr int RNK  = 4;      // low rank
constexpr int DIN  = 128;
constexpr int DOUT = 128;
constexpr int BATCH = 32;
constexpr int T    = 8192;
constexpr int L    = 64;             // chunk length
constexpr int G    = T / L;          // 128 chunks
constexpr int NPOW = 6;              // log2(L)
constexpr int BT   = BATCH * T;      // 262144
constexpr int PF   = 4;              // scan prefetch depth (compile-time ring)

// ---------------- device scratch (static, no allocs) ----------------
__device__ float2 g_bu[(size_t)BT * N];      // 128 MB : B_d @ u  (complex)
__device__ float  g_xr[(size_t)BT * N];      // 64 MB  : Re(x_t)
__device__ float2 g_Bd[DIN * N];             // B_d transposed: [i][n]
__device__ float2 g_Da[N];
__device__ float2 g_U[N * RNK];
__device__ float2 g_V[RNK * N];
__device__ float2 g_Ad[N * N];
__device__ float2 g_Atmp[N * N];
__device__ float2 g_csum[BATCH * G * N];
__device__ float2 g_xin[BATCH * G * N];
__device__ float  g_CT[N * DOUT];            // C transposed: [k][o]
__device__ float  g_DT[DIN * DOUT];          // D transposed: [k][o]
__device__ int    g_dflag;

// ---------------- helpers ----------------
__device__ __forceinline__ float2 cfma(float2 a, float2 b, float2 c) { // c + a*b
    float2 r;
    r.x = fmaf(a.x, b.x, fmaf(-a.y, b.y, c.x));
    r.y = fmaf(a.x, b.y, fmaf( a.y, b.x, c.y));
    return r;
}
__device__ __forceinline__ float2 cmulf(float2 a, float2 b) {
    return cfma(a, b, make_float2(0.f, 0.f));
}
__device__ __forceinline__ unsigned long long ffma2(unsigned long long a,
                                                    unsigned long long b,
                                                    unsigned long long c) {
    unsigned long long d;
    asm("fma.rn.f32x2 %0, %1, %2, %3;" : "=l"(d) : "l"(a), "l"(b), "l"(c));
    return d;
}
__device__ __forceinline__ unsigned long long pack2(float x, float y) {
    unsigned long long r;
    asm("mov.b64 %0, {%1, %2};" : "=l"(r) : "f"(x), "f"(y));
    return r;
}
__device__ __forceinline__ float2 unpack2(unsigned long long v) {
    float x, y;
    asm("mov.b64 {%0, %1}, %2;" : "=f"(x), "=f"(y) : "l"(v));
    return make_float2(x, y);
}

// ---------------- setup: Woodbury factors, B_d, dense A_d, transposes, dflag ----------------
__global__ void setup_kernel(const float* __restrict__ lw, const float* __restrict__ zl,
                             const float* __restrict__ P,  const float* __restrict__ Q,
                             const float* __restrict__ Bm, const float* __restrict__ C,
                             const float* __restrict__ D) {
    __shared__ float2 sminv[N];
    __shared__ float2 sS[16];
    __shared__ float2 sK[16];
    __shared__ float2 sW[RNK * DIN];
    __shared__ float  sred[128];
    const float c = 0.5f * DT_F;
    const int t = threadIdx.x;   // 128 threads

    if (t < N) {
        float om = expf(lw[t]);
        float ze = 1.f / (1.f + expf(-zl[t]));
        float lr = -ze * om;
        float li = om * sqrtf(fmaxf(1.f - ze * ze, 1e-8f));
        float mr = 1.f - c * lr;
        float mi = -c * li;
        float inv = 1.f / (mr * mr + mi * mi);
        sminv[t] = make_float2(mr * inv, -mi * inv);
    }
    __syncthreads();

    // S = c * Q^T Minv P  (4x4 complex)
    if (t < 16) {
        int r = t >> 2, s2 = t & 3;
        float2 acc = make_float2(0.f, 0.f);
        for (int k = 0; k < N; k++) {
            float coef = Q[k * RNK + r] * P[k * RNK + s2];
            acc.x += coef * sminv[k].x;
            acc.y += coef * sminv[k].y;
        }
        sS[t] = make_float2(c * acc.x, c * acc.y);
    }
    __syncthreads();

    // K = inv(I4 - S), Gauss-Jordan
    if (t == 0) {
        float2 M_[4][8];
        for (int i = 0; i < 4; i++)
            for (int j = 0; j < 4; j++) {
                float2 v = sS[i * 4 + j];
                M_[i][j] = make_float2((i == j ? 1.f : 0.f) - v.x, -v.y);
                M_[i][4 + j] = make_float2(i == j ? 1.f : 0.f, 0.f);
            }
        for (int col = 0; col < 4; col++) {
            float2 p = M_[col][col];
            float d = 1.f / (p.x * p.x + p.y * p.y);
            float2 pinv = make_float2(p.x * d, -p.y * d);
            for (int j = 0; j < 8; j++) M_[col][j] = cmulf(M_[col][j], pinv);
            for (int rr = 0; rr < 4; rr++)
                if (rr != col) {
                    float2 f = M_[rr][col];
                    for (int j = 0; j < 8; j++) {
                        float2 s = cmulf(f, M_[col][j]);
                        M_[rr][j].x -= s.x;
                        M_[rr][j].y -= s.y;
                    }
                }
        }
        for (int i = 0; i < 4; i++)
            for (int j = 0; j < 4; j++) sK[i * 4 + j] = M_[i][4 + j];
    }
    __syncthreads();

    // Da, U, V
    if (t < N) {
        float2 mv = sminv[t];
        g_Da[t] = make_float2(2.f * mv.x - 1.f, 2.f * mv.y);
        #pragma unroll
        for (int r = 0; r < RNK; r++) {
            float2 pk = make_float2(0.f, 0.f);
            #pragma unroll
            for (int s2 = 0; s2 < RNK; s2++) {
                float pv = P[t * RNK + s2];
                pk.x += pv * sK[s2 * 4 + r].x;
                pk.y += pv * sK[s2 * 4 + r].y;
            }
            float2 u = cmulf(make_float2(2.f * c * mv.x, 2.f * c * mv.y), pk);
            g_U[t * RNK + r] = u;
            float qv = Q[t * RNK + r];
            g_V[r * N + t] = make_float2(qv * mv.x, qv * mv.y);
        }
    }
    __syncthreads();

    // W[r][i] = sum_k V[r][k] * B[k][i]
    {
        int i = t;
        #pragma unroll
        for (int r = 0; r < RNK; r++) {
            float2 acc = make_float2(0.f, 0.f);
            for (int k = 0; k < N; k++) {
                float coef = Q[k * RNK + r] * Bm[k * DIN + i];
                acc.x += coef * sminv[k].x;
                acc.y += coef * sminv[k].y;
            }
            sW[r * DIN + i] = acc;
        }
    }
    __syncthreads();

    // B_d (transposed store)
    const float sq = sqrtf(DT_F);
    for (int idx = t; idx < N * DIN; idx += 128) {
        int j = idx >> 7, i = idx & 127;
        float2 mv = sminv[j];
        float bv = Bm[j * DIN + i];
        float2 acc = make_float2(bv * mv.x, bv * mv.y);
        #pragma unroll
        for (int r = 0; r < RNK; r++) {
            float2 u = g_U[j * RNK + r];
            acc = cfma(make_float2(0.5f * u.x, 0.5f * u.y), sW[r * DIN + i], acc);
        }
        g_Bd[i * N + j] = make_float2(sq * acc.x, sq * acc.y);
    }
    // dense A_d
    for (int idx = t; idx < N * N; idx += 128) {
        int j = idx >> 6, k = idx & 63;
        float2 acc = (j == k) ? g_Da[j] : make_float2(0.f, 0.f);
        #pragma unroll
        for (int r = 0; r < RNK; r++) acc = cfma(g_U[j * RNK + r], g_V[r * N + k], acc);
        g_Ad[j * N + k] = acc;
    }
    // transposes
    for (int idx = t; idx < DOUT * N; idx += 128) {
        int o = idx & 127, k = idx >> 7;
        g_CT[k * DOUT + o] = C[o * N + k];
    }
    for (int idx = t; idx < DOUT * DIN; idx += 128) {
        int o = idx & 127, k = idx >> 7;
        g_DT[k * DOUT + o] = D[o * DIN + k];
    }
    // D-zero flag
    {
        float s = 0.f;
        for (int i = t; i < DOUT * DIN; i += 128) s += fabsf(D[i]);
        sred[t] = s;
        __syncthreads();
        for (int st = 64; st > 0; st >>= 1) {
            if (t < st) sred[t] += sred[t + st];
            __syncthreads();
        }
        if (t == 0) g_dflag = (sred[0] != 0.f) ? 1 : 0;
    }
}

// ---------------- A_d^L via NPOW squarings inside ONE cluster kernel ----------------
// NPOW=6: iterations it=0..5, last (it=5, odd) writes g_Ad -> A_d^64 in g_Ad.
__global__ void __cluster_dims__(8, 1, 1) __launch_bounds__(128) power_kernel() {
    const int t = threadIdx.x;
    const int cr = blockIdx.x;
    const int row = cr * 8 + (t >> 4);
    const int col = (t & 15) * 4;

    #pragma unroll 1
    for (int it = 0; it < NPOW; it++) {
        const float2* src = (it & 1) ? g_Atmp : g_Ad;
        float2*       dst = (it & 1) ? g_Ad : g_Atmp;
        float2 a0 = make_float2(0.f, 0.f), a1 = a0, a2 = a0, a3 = a0;
        #pragma unroll 8
        for (int k = 0; k < N; k++) {
            float2 av = __ldcg(&src[row * N + k]);
            const float4* bp = (const float4*)&src[k * N + col];
            float4 b01 = __ldcg(&bp[0]);
            float4 b23 = __ldcg(&bp[1]);
            a0 = cfma(av, make_float2(b01.x, b01.y), a0);
            a1 = cfma(av, make_float2(b01.z, b01.w), a1);
            a2 = cfma(av, make_float2(b23.x, b23.y), a2);
            a3 = cfma(av, make_float2(b23.z, b23.w), a3);
        }
        dst[row * N + col + 0] = a0;
        dst[row * N + col + 1] = a1;
        dst[row * N + col + 2] = a2;
        dst[row * N + col + 3] = a3;
        __threadfence();
        asm volatile("barrier.cluster.arrive.aligned;" ::: "memory");
        asm volatile("barrier.cluster.wait.aligned;" ::: "memory");
    }
}

// ---------------- bu = u @ B_d^T  (complex out), packed f32x2 GEMM ----------------
__global__ __launch_bounds__(256) void bu_gemm_kernel(const float* __restrict__ u) {
    __shared__ float  su[32][132];   // padded: row stride 528 B, float4-aligned
    __shared__ float2 sb[32][66];
    const int tid = threadIdx.x;
    const int tx = tid & 15, ty = tid >> 4;
    const size_t bt0 = (size_t)blockIdx.x * 128;

    unsigned long long acc[8][4];
    #pragma unroll
    for (int i = 0; i < 8; i++)
        #pragma unroll
        for (int j = 0; j < 4; j++) acc[i][j] = 0ull;

    for (int k0 = 0; k0 < DIN; k0 += 32) {
        #pragma unroll
        for (int l = 0; l < 4; l++) {
            int idx = tid + l * 256;
            int row = idx >> 3, k4 = idx & 7;
            float4 v = *(const float4*)&u[(bt0 + row) * DIN + k0 + k4 * 4];
            su[k4 * 4 + 0][row] = v.x;
            su[k4 * 4 + 1][row] = v.y;
            su[k4 * 4 + 2][row] = v.z;
            su[k4 * 4 + 3][row] = v.w;
        }
        #pragma unroll
        for (int l = 0; l < 4; l++) {
            int idx = tid + l * 256;
            int nn2 = idx & 31, kk = idx >> 5;
            float4 v = *(const float4*)&g_Bd[(k0 + kk) * N + nn2 * 2];
            *(float4*)&sb[kk][nn2 * 2] = v;
        }
        __syncthreads();
        #pragma unroll
        for (int k = 0; k < 32; k++) {
            float4 q0 = *(const float4*)&su[k][ty * 8];
            float4 q1 = *(const float4*)&su[k][ty * 8 + 4];
            unsigned long long a8[8];
            a8[0] = pack2(q0.x, q0.x); a8[1] = pack2(q0.y, q0.y);
            a8[2] = pack2(q0.z, q0.z); a8[3] = pack2(q0.w, q0.w);
            a8[4] = pack2(q1.x, q1.x); a8[5] = pack2(q1.y, q1.y);
            a8[6] = pack2(q1.z, q1.z); a8[7] = pack2(q1.w, q1.w);
            double2 w0 = *(const double2*)&sb[k][tx * 4];
            double2 w1 = *(const double2*)&sb[k][tx * 4 + 2];
            unsigned long long b4[4];
            b4[0] = __double_as_longlong(w0.x); b4[1] = __double_as_longlong(w0.y);
            b4[2] = __double_as_longlong(w1.x); b4[3] = __double_as_longlong(w1.y);
            #pragma unroll
            for (int i = 0; i < 8; i++)
                #pragma unroll
                for (int j = 0; j < 4; j++) acc[i][j] = ffma2(a8[i], b4[j], acc[i][j]);
        }
        __syncthreads();
    }
    #pragma unroll
    for (int i = 0; i < 8; i++) {
        #pragma unroll
        for (int jj = 0; jj < 2; jj++) {
            float2 lo = unpack2(acc[i][2 * jj]);
            float2 hi = unpack2(acc[i][2 * jj + 1]);
            float4 v = make_float4(lo.x, lo.y, hi.x, hi.y);
            *(float4*)&g_bu[(bt0 + ty * 8 + i) * N + tx * 4 + 2 * jj] = v;
        }
    }
}

// ---------------- chunked scan, f32x2-packed + shfl butterfly reductions ----------------
// mode 0: local sums from zero -> g_csum ; mode 1: final pass from g_xin -> g_xr
__global__ __launch_bounds__(128) void scan_kernel(int mode) {
    const int w  = blockIdx.x * 4 + (threadIdx.x >> 5);
    const int ln = threadIdx.x & 31;
    const int b = w >> 7;        // / G (G=128)
    const int g = w & 127;       // % G
    const size_t bt0 = (size_t)b * T + (size_t)g * L;
    typedef unsigned long long ull;

    // packed constants: slot.lo = state ln, slot.hi = state ln+32
    float2 Da0 = g_Da[ln], Da1 = g_Da[ln + 32];
    ull da_r  = pack2(Da0.x, Da1.x);
    ull da_i  = pack2(Da0.y, Da1.y);
    ull da_iN = pack2(-Da0.y, -Da1.y);
    ull ur[RNK], ui[RNK], uiN[RNK], vr[RNK], vi[RNK], viN[RNK];
    #pragma unroll
    for (int r = 0; r < RNK; r++) {
        float2 U0 = g_U[ln * RNK + r], U1 = g_U[(ln + 32) * RNK + r];
        float2 V0 = g_V[r * N + ln],   V1 = g_V[r * N + ln + 32];
        ur[r]  = pack2(U0.x, U1.x);
        ui[r]  = pack2(U0.y, U1.y);
        uiN[r] = pack2(-U0.y, -U1.y);
        vr[r]  = pack2(V0.x, V1.x);
        vi[r]  = pack2(V0.y, V1.y);
        viN[r] = pack2(-V0.y, -V1.y);
    }

    ull xr = 0ull, xi = 0ull;
    if (mode) {
        int ci = (b * G + g) * N;
        float2 x0 = g_xin[ci + ln], x1 = g_xin[ci + ln + 32];
        xr = pack2(x0.x, x1.x);
        xi = pack2(x0.y, x1.y);
    }

    const float2* bup = g_bu + bt0 * N;
    float2 pb0[PF], pb1[PF];
    #pragma unroll
    for (int j = 0; j < PF; j++) {
        pb0[j] = bup[j * N + ln];
        pb1[j] = bup[j * N + ln + 32];
    }

    const ull zero = 0ull;
    #pragma unroll 1
    for (int t0 = 0; t0 < L; t0 += PF) {
        #pragma unroll
        for (int j = 0; j < PF; j++) {           // compile-time ring index -> registers
            const int t = t0 + j;
            float2 c0 = pb0[j], c1 = pb1[j];
            if (t + PF < L) {
                pb0[j] = bup[(t + PF) * N + ln];
                pb1[j] = bup[(t + PF) * N + ln + 32];
            }
            // rank partials  s[r] = sum_n V[r][n] x[n]
            float sre[RNK], sim[RNK];
            #pragma unroll
            for (int r = 0; r < RNK; r++) {
                ull pr = ffma2(viN[r], xi, ffma2(vr[r], xr, zero));
                ull pi = ffma2(vi[r],  xr, ffma2(vr[r], xi, zero));
                float2 a  = unpack2(pr);
                float2 bb = unpack2(pi);
                sre[r] = a.x + a.y;
                sim[r] = bb.x + bb.y;
            }
            // warp-wide sum: 5-level butterfly, 8 independent chains for ILP
            #pragma unroll
            for (int off = 16; off > 0; off >>= 1) {
                #pragma unroll
                for (int r = 0; r < RNK; r++) {
                    sre[r] += __shfl_xor_sync(0xffffffffu, sre[r], off);
                    sim[r] += __shfl_xor_sync(0xffffffffu, sim[r], off);
                }
            }
            ull bur = pack2(c0.x, c1.x);
            ull bui = pack2(c0.y, c1.y);
            ull yr = ffma2(da_r, xr, ffma2(da_iN, xi, bur));
            ull yi = ffma2(da_r, xi, ffma2(da_i,  xr, bui));
            #pragma unroll
            for (int r = 0; r < RNK; r++) {
                ull pr = pack2(sre[r], sre[r]);
                ull pi = pack2(sim[r], sim[r]);
                yr = ffma2(uiN[r], pi, ffma2(ur[r], pr, yr));
                yi = ffma2(ui[r],  pr, ffma2(ur[r], pi, yi));
            }
            xr = yr;
            xi = yi;
            if (mode) {
                float2 o = unpack2(xr);
                g_xr[(bt0 + t) * N + ln]      = o.x;
                g_xr[(bt0 + t) * N + ln + 32] = o.y;
            }
        }
    }
    if (!mode) {
        int ci = (b * G + g) * N;
        float2 rr = unpack2(xr), i2 = unpack2(xi);
        g_csum[ci + ln]      = make_float2(rr.x, i2.x);
        g_csum[ci + ln + 32] = make_float2(rr.y, i2.y);
    }
}

// ---------------- chunk-level chain: x_in[g+1] = A^L x_in[g] + c_g ----------------
__global__ __launch_bounds__(64) void chain_kernel() {
    __shared__ float2 sA[N * 65];
    __shared__ float2 sx[N];
    const int b = blockIdx.x, t = threadIdx.x;
    for (int i = t; i < N * N; i += 64) {
        int r = i >> 6, c = i & 63;
        sA[r * 65 + c] = g_Ad[i];   // A^64 (NPOW=6 -> result in g_Ad)
    }
    float2 x = make_float2(0.f, 0.f);
    for (int g = 0; g < G; g++) {
        int ci = (b * G + g) * N;
        g_xin[ci + t] = x;
        sx[t] = x;
        __syncthreads();
        float2 a0 = g_csum[ci + t];
        float2 a1 = make_float2(0.f, 0.f), a2 = a1, a3 = a1;
        #pragma unroll 4
        for (int k = 0; k < N; k += 4) {
            a0 = cfma(sA[t * 65 + k + 0], sx[k + 0], a0);
            a1 = cfma(sA[t * 65 + k + 1], sx[k + 1], a1);
            a2 = cfma(sA[t * 65 + k + 2], sx[k + 2], a2);
            a3 = cfma(sA[t * 65 + k + 3], sx[k + 3], a3);
        }
        x.x = (a0.x + a1.x) + (a2.x + a3.x);
        x.y = (a0.y + a1.y) + (a2.y + a3.y);
        __syncthreads();
    }
}

// ---------------- y = Re(x) @ C^T (+ u @ D^T if D != 0), packed f32x2 GEMM ----------------
__global__ __launch_bounds__(256) void y_gemm_kernel(const float* __restrict__ u,
                                                     float* __restrict__ out) {
    __shared__ float sx[32][132];
    __shared__ float sc[32][132];
    const int tid = threadIdx.x;
    const int tx = tid & 15, ty = tid >> 4;
    const size_t bt0 = (size_t)blockIdx.x * 128;

    unsigned long long acc[8][4];
    #pragma unroll
    for (int i = 0; i < 8; i++)
        #pragma unroll
        for (int j = 0; j < 4; j++) acc[i][j] = 0ull;

    for (int k0 = 0; k0 < N; k0 += 32) {
        #pragma unroll
        for (int l = 0; l < 4; l++) {
            int idx = tid + l * 256;
            int row = idx >> 3, k4 = idx & 7;
            float4 v = *(const float4*)&g_xr[(bt0 + row) * N + k0 + k4 * 4];
            sx[k4 * 4 + 0][row] = v.x;
            sx[k4 * 4 + 1][row] = v.y;
            sx[k4 * 4 + 2][row] = v.z;
            sx[k4 * 4 + 3][row] = v.w;
        }
        #pragma unroll
        for (int l = 0; l < 4; l++) {
            int idx = tid + l * 256;
            int o4 = idx & 31, kk = idx >> 5;
            float4 v = *(const float4*)&g_CT[(k0 + kk) * DOUT + o4 * 4];
            *(float4*)&sc[kk][o4 * 4] = v;
        }
        __syncthreads();
        #pragma unroll
        for (int k = 0; k < 32; k++) {
            float4 q0 = *(const float4*)&sx[k][ty * 8];
            float4 q1 = *(const float4*)&sx[k][ty * 8 + 4];
            unsigned long long a8[8];
            a8[0] = pack2(q0.x, q0.x); a8[1] = pack2(q0.y, q0.y);
            a8[2] = pack2(q0.z, q0.z); a8[3] = pack2(q0.w, q0.w);
            a8[4] = pack2(q1.x, q1.x); a8[5] = pack2(q1.y, q1.y);
            a8[6] = pack2(q1.z, q1.z); a8[7] = pack2(q1.w, q1.w);
            double2 w0 = *(const double2*)&sc[k][tx * 8];
            double2 w1 = *(const double2*)&sc[k][tx * 8 + 4];
            unsigned long long b4[4];
            b4[0] = __double_as_longlong(w0.x); b4[1] = __double_as_longlong(w0.y);
            b4[2] = __double_as_longlong(w1.x); b4[3] = __double_as_longlong(w1.y);
            #pragma unroll
            for (int i = 0; i < 8; i++)
                #pragma unroll
                for (int j = 0; j < 4; j++) acc[i][j] = ffma2(a8[i], b4[j], acc[i][j]);
        }
        __syncthreads();
    }
    if (g_dflag) {
        for (int k0 = 0; k0 < DIN; k0 += 32) {
            #pragma unroll
            for (int l = 0; l < 4; l++) {
                int idx = tid + l * 256;
                int row = idx >> 3, k4 = idx & 7;
                float4 v = *(const float4*)&u[(bt0 + row) * DIN + k0 + k4 * 4];
                sx[k4 * 4 + 0][row] = v.x;
                sx[k4 * 4 + 1][row] = v.y;
                sx[k4 * 4 + 2][row] = v.z;
                sx[k4 * 4 + 3][row] = v.w;
            }
            #pragma unroll
            for (int l = 0; l < 4; l++) {
                int idx = tid + l * 256;
                int o4 = idx & 31, kk = idx >> 5;
                float4 v = *(const float4*)&g_DT[(k0 + kk) * DOUT + o4 * 4];
                *(float4*)&sc[kk][o4 * 4] = v;
            }
            __syncthreads();
            #pragma unroll
            for (int k = 0; k < 32; k++) {
                float4 q0 = *(const float4*)&sx[k][ty * 8];
                float4 q1 = *(const float4*)&sx[k][ty * 8 + 4];
                unsigned long long a8[8];
                a8[0] = pack2(q0.x, q0.x); a8[1] = pack2(q0.y, q0.y);
                a8[2] = pack2(q0.z, q0.z); a8[3] = pack2(q0.w, q0.w);
                a8[4] = pack2(q1.x, q1.x); a8[5] = pack2(q1.y, q1.y);
                a8[6] = pack2(q1.z, q1.z); a8[7] = pack2(q1.w, q1.w);
                double2 w0 = *(const double2*)&sc[k][tx * 8];
                double2 w1 = *(const double2*)&sc[k][tx * 8 + 4];
                unsigned long long b4[4];
                b4[0] = __double_as_longlong(w0.x); b4[1] = __double_as_longlong(w0.y);
                b4[2] = __double_as_longlong(w1.x); b4[3] = __double_as_longlong(w1.y);
                #pragma unroll
                for (int i = 0; i < 8; i++)
                    #pragma unroll
                    for (int j = 0; j < 4; j++) acc[i][j] = ffma2(a8[i], b4[j], acc[i][j]);
            }
            __syncthreads();
        }
    }
    #pragma unroll
    for (int i = 0; i < 8; i++) {
        float2 p0 = unpack2(acc[i][0]);
        float2 p1 = unpack2(acc[i][1]);
        float2 p2 = unpack2(acc[i][2]);
        float2 p3 = unpack2(acc[i][3]);
        float4 v0 = make_float4(p0.x, p0.y, p1.x, p1.y);
        float4 v1 = make_float4(p2.x, p2.y, p3.x, p3.y);
        size_t base = (bt0 + ty * 8 + i) * DOUT + tx * 8;
        *(float4*)&out[base]     = v0;
        *(float4*)&out[base + 4] = v1;
    }
}

// ---------------- launch ----------------
extern "C" void kernel_launch(void* const* d_in, const int* in_sizes, int n_in,
                              void* d_out, int out_size) {
    const float* u  = (const float*)d_in[0];
    const float* lw = (const float*)d_in[1];
    const float* zl = (const float*)d_in[2];
    const float* P  = (const float*)d_in[3];
    const float* Q  = (const float*)d_in[4];
    const float* Bm = (const float*)d_in[5];
    const float* C  = (const float*)d_in[6];
    const float* D  = (const float*)d_in[7];
    float* out = (float*)d_out;

    setup_kernel<<<1, 128>>>(lw, zl, P, Q, Bm, C, D);
    power_kernel<<<8, 128>>>();                 // A_d^64 -> g_Ad (one cluster launch)
    bu_gemm_kernel<<<BT / 128, 256>>>(u);
    scan_kernel<<<(BATCH * G) / 4, 128>>>(0);   // local chunk sums (4096 chunks)
    chain_kernel<<<BATCH, 64>>>();              // chunk-level recurrence (G=128 steps)
    scan_kernel<<<(BATCH * G) / 4, 128>>>(1);   // final pass, store Re(x)
    y_gemm_kernel<<<BT / 128, 256>>>(u, out);
}